// round 1
// baseline (speedup 1.0000x reference)
#include <cuda_runtime.h>

// Problem constants
#define NROWS 16384          // B*S = 64*256
#define DIMV  512
#define NQ    8
#define NK    1024
#define NDTOT (NROWS*DIMV)   // 8388608

// Static device scratch (no allocations allowed)
__device__ float  g_res[NDTOT];          // residual, 32 MB
__device__ int    g_idx[NROWS];          // argmin indices for current step
__device__ float  g_enorm[NQ*NK];        // ||e||^2 per code
__device__ double g_loss_part[NQ*128];   // per-(step,block) loss partials

// ---------------------------------------------------------------------------
// Copy x -> residual (float4 grid-stride, exact cover: 8192*256 = 2M float4)
// ---------------------------------------------------------------------------
__global__ void copy_res_kernel(const float* __restrict__ x) {
    int i = blockIdx.x * blockDim.x + threadIdx.x;   // 0 .. 2097151
    reinterpret_cast<float4*>(g_res)[i] =
        reinterpret_cast<const float4*>(x)[i];
}

// ---------------------------------------------------------------------------
// ||e_k||^2 for all 8192 codes: one warp per code
// ---------------------------------------------------------------------------
__global__ void enorm_kernel(const float* __restrict__ emb) {
    int gwarp = (blockIdx.x * blockDim.x + threadIdx.x) >> 5;  // 0..8191
    int lane  = threadIdx.x & 31;
    const float* e = emb + (size_t)gwarp * DIMV;
    float s = 0.f;
    #pragma unroll
    for (int d = lane; d < DIMV; d += 32) {
        float v = e[d];
        s += v * v;
    }
    #pragma unroll
    for (int off = 16; off > 0; off >>= 1)
        s += __shfl_down_sync(0xffffffffu, s, off);
    if (lane == 0) g_enorm[gwarp] = s;
}

// ---------------------------------------------------------------------------
// Fused distance GEMM + argmin.
// Block: 64 rows x all 1024 codes, code tiles of 64, d tiles of 16.
// 256 threads, 4x4 micro-tile per thread. dist_cmp = ||e||^2 - 2 r.e
// (per-row ||r||^2 constant dropped; argmin-invariant).
// Tie-break: first (lowest) index, matching jnp.argmin.
// ---------------------------------------------------------------------------
__global__ __launch_bounds__(256) void dist_argmin_kernel(
    const float* __restrict__ E,      // codebook for this step [1024,512]
    int qstep)
{
    __shared__ float As[16][64];      // [d][row]
    __shared__ float Bs[16][64];      // [d][code]
    __shared__ float sMin[64][17];
    __shared__ int   sIdx[64][17];

    const int t  = threadIdx.x;
    const int tx = t & 15;            // code group
    const int ty = t >> 4;            // row group
    const int rowBase = blockIdx.x * 64;

    float best[4];
    int   bidx[4];
    #pragma unroll
    for (int i = 0; i < 4; ++i) { best[i] = 3.4e38f; bidx[i] = 0; }

    const float* enormq = g_enorm + qstep * NK;

    for (int ct = 0; ct < 16; ++ct) {
        const int cBase = ct * 64;
        float acc[4][4];
        #pragma unroll
        for (int i = 0; i < 4; ++i)
            #pragma unroll
            for (int j = 0; j < 4; ++j) acc[i][j] = 0.f;

        for (int dt = 0; dt < 32; ++dt) {
            const int d0 = dt * 16;
            __syncthreads();
            #pragma unroll
            for (int i = 0; i < 4; ++i) {
                int lin = t + 256 * i;          // 0..1023
                int dd  = lin & 15;
                int rr  = lin >> 4;             // 0..63
                As[dd][rr] = g_res[(size_t)(rowBase + rr) * DIMV + d0 + dd];
                Bs[dd][rr] = E[(size_t)(cBase + rr) * DIMV + d0 + dd];
            }
            __syncthreads();
            #pragma unroll
            for (int dd = 0; dd < 16; ++dd) {
                const float4 a = *reinterpret_cast<const float4*>(&As[dd][ty * 4]);
                const float4 b = *reinterpret_cast<const float4*>(&Bs[dd][tx * 4]);
                const float av[4] = {a.x, a.y, a.z, a.w};
                const float bv[4] = {b.x, b.y, b.z, b.w};
                #pragma unroll
                for (int i = 0; i < 4; ++i)
                    #pragma unroll
                    for (int j = 0; j < 4; ++j)
                        acc[i][j] += av[i] * bv[j];
            }
        }

        // compare against running min (ascending code index => strict <
        // keeps the first occurrence, matching jnp.argmin)
        #pragma unroll
        for (int j = 0; j < 4; ++j) {
            const int c = cBase + tx * 4 + j;
            const float en = enormq[c];
            #pragma unroll
            for (int i = 0; i < 4; ++i) {
                const float d = en - 2.f * acc[i][j];
                if (d < best[i]) { best[i] = d; bidx[i] = c; }
            }
        }
    }

    __syncthreads();
    #pragma unroll
    for (int i = 0; i < 4; ++i) {
        const int row = ty * 4 + i;
        sMin[row][tx] = best[i];
        sIdx[row][tx] = bidx[i];
    }
    __syncthreads();

    if (t < 64) {
        float m  = sMin[t][0];
        int   mi = sIdx[t][0];
        #pragma unroll
        for (int k = 1; k < 16; ++k) {
            const float v  = sMin[t][k];
            const int   vi = sIdx[t][k];
            if (v < m || (v == m && vi < mi)) { m = v; mi = vi; }
        }
        g_idx[rowBase + t] = mi;
    }
}

// ---------------------------------------------------------------------------
// Residual update: r -= e[idx]; accumulate sum(r_new^2) (loss partials);
// write index (as float) into the output's indices region.
// 128 blocks x 256 threads; each block handles 128 rows (2 rows in flight).
// ---------------------------------------------------------------------------
__global__ __launch_bounds__(256) void update_kernel(
    const float* __restrict__ E,      // codebook for this step
    float* __restrict__ outF,
    int qstep)
{
    const int tid  = threadIdx.x;
    const int sub  = tid >> 7;        // 0/1: which of the two concurrent rows
    const int lane = tid & 127;       // float4 lane within a row (128*4 = 512)
    const int rowBase = blockIdx.x * 128;

    double s = 0.0;
    for (int it = 0; it < 64; ++it) {
        const int row = rowBase + it * 2 + sub;
        const int id  = g_idx[row];
        float4* r4 = reinterpret_cast<float4*>(g_res + (size_t)row * DIMV);
        const float4* e4 =
            reinterpret_cast<const float4*>(E + (size_t)id * DIMV);
        float4 r = r4[lane];
        const float4 e = e4[lane];
        r.x -= e.x; r.y -= e.y; r.z -= e.z; r.w -= e.w;
        r4[lane] = r;
        s += (double)(r.x * r.x + r.y * r.y + r.z * r.z + r.w * r.w);
        if (lane == 0)
            outF[NDTOT + row * NQ + qstep] = (float)id;
    }

    // block reduce (8 warps)
    #pragma unroll
    for (int off = 16; off > 0; off >>= 1)
        s += __shfl_down_sync(0xffffffffu, s, off);
    __shared__ double ws[8];
    const int wid = tid >> 5, ln = tid & 31;
    if (ln == 0) ws[wid] = s;
    __syncthreads();
    if (tid == 0) {
        double tot = 0.0;
        #pragma unroll
        for (int w = 0; w < 8; ++w) tot += ws[w];
        g_loss_part[qstep * 128 + blockIdx.x] = tot;
    }
}

// ---------------------------------------------------------------------------
// qout = x - r_final; write total loss.
// ---------------------------------------------------------------------------
__global__ void finalize_kernel(const float* __restrict__ x,
                                float* __restrict__ outF)
{
    const int i = blockIdx.x * blockDim.x + threadIdx.x;  // 0..2097151
    const float4 xv = reinterpret_cast<const float4*>(x)[i];
    const float4 rv = reinterpret_cast<const float4*>(g_res)[i];
    float4 o;
    o.x = xv.x - rv.x; o.y = xv.y - rv.y;
    o.z = xv.z - rv.z; o.w = xv.w - rv.w;
    reinterpret_cast<float4*>(outF)[i] = o;

    if (blockIdx.x == 0 && threadIdx.x == 0) {
        double tot = 0.0;
        #pragma unroll 8
        for (int k = 0; k < NQ * 128; ++k) tot += g_loss_part[k];
        outF[NDTOT + NROWS * NQ] = (float)(2.0 * tot / (double)NDTOT);
    }
}

// ---------------------------------------------------------------------------
extern "C" void kernel_launch(void* const* d_in, const int* in_sizes, int n_in,
                              void* d_out, int out_size)
{
    const float* x   = (const float*)d_in[0];   // [64,256,512]
    const float* emb = (const float*)d_in[1];   // [8,1024,512]
    float* outF = (float*)d_out;                // [qout | indices | loss]

    copy_res_kernel<<<8192, 256>>>(x);
    enorm_kernel<<<1024, 256>>>(emb);

    for (int q = 0; q < NQ; ++q) {
        const float* Eq = emb + (size_t)q * NK * DIMV;
        dist_argmin_kernel<<<256, 256>>>(Eq, q);
        update_kernel<<<128, 256>>>(Eq, outF, q);
    }

    finalize_kernel<<<8192, 256>>>(x, outF);
}

// round 3
// speedup vs baseline: 3.1867x; 3.1867x over previous
#include <cuda_runtime.h>
#include <cuda_bf16.h>

#define NROWS 16384          // B*S
#define DIMV  512
#define NQ    8
#define NK    1024
#define NDTOT (NROWS*DIMV)   // 8388608
#define NETOT (NQ*NK*DIMV)   // 4194304

// ------------------------- device scratch (no allocs) ----------------------
__device__ float  g_res[NDTOT];            // fp32 residual
__device__ int    g_idx[NROWS];            // per-step argmin indices
__device__ float  g_enorm[NQ*NK];          // ||e||^2 fp32
__device__ double g_loss_part[NQ*512];     // loss partials
// bf16 3-way splits, stored as uint4 (8 bf16) for vector access
__device__ uint4  g_rh[NDTOT/8], g_rm[NDTOT/8], g_rl[NDTOT/8];
__device__ uint4  g_eh[NETOT/8], g_em[NETOT/8], g_el[NETOT/8];

// ------------------------- PTX helpers (sm_80-compatible only) --------------
__device__ __forceinline__ unsigned smem_u32(const void* p) {
    unsigned a;
    asm("{ .reg .u64 t; cvta.to.shared.u64 t, %1; cvt.u32.u64 %0, t; }"
        : "=r"(a) : "l"(p));
    return a;
}
__device__ __forceinline__ void ldsm4(unsigned* r, unsigned addr) {
    asm volatile("ldmatrix.sync.aligned.m8n8.x4.shared.b16 {%0,%1,%2,%3}, [%4];"
        : "=r"(r[0]), "=r"(r[1]), "=r"(r[2]), "=r"(r[3]) : "r"(addr));
}
__device__ __forceinline__ void mma16816(float* c, const unsigned* a,
                                         unsigned b0, unsigned b1) {
    asm volatile(
        "mma.sync.aligned.m16n8k16.row.col.f32.bf16.bf16.f32 "
        "{%0,%1,%2,%3}, {%4,%5,%6,%7}, {%8,%9}, {%0,%1,%2,%3};"
        : "+f"(c[0]), "+f"(c[1]), "+f"(c[2]), "+f"(c[3])
        : "r"(a[0]), "r"(a[1]), "r"(a[2]), "r"(a[3]), "r"(b0), "r"(b1));
}

// ------------------------- bf16 3-way split ---------------------------------
__device__ __forceinline__ void split3(float v, unsigned short& h,
                                       unsigned short& m, unsigned short& l) {
    __nv_bfloat16 bh = __float2bfloat16(v);
    float fh = __bfloat162float(bh);
    __nv_bfloat16 bm = __float2bfloat16(v - fh);
    float fm = __bfloat162float(bm);
    __nv_bfloat16 bl = __float2bfloat16(v - fh - fm);
    h = *reinterpret_cast<unsigned short*>(&bh);
    m = *reinterpret_cast<unsigned short*>(&bm);
    l = *reinterpret_cast<unsigned short*>(&bl);
}
__device__ __forceinline__ uint2 pack4(const unsigned short* s) {
    return make_uint2((unsigned)s[0] | ((unsigned)s[1] << 16),
                      (unsigned)s[2] | ((unsigned)s[3] << 16));
}

// ------------------------- setup kernels -------------------------------------
__global__ void copy_split_kernel(const float* __restrict__ x) {
    int i = blockIdx.x * blockDim.x + threadIdx.x;       // 0..2097151
    float4 v = reinterpret_cast<const float4*>(x)[i];
    reinterpret_cast<float4*>(g_res)[i] = v;
    unsigned short h[4], m[4], l[4];
    split3(v.x, h[0], m[0], l[0]); split3(v.y, h[1], m[1], l[1]);
    split3(v.z, h[2], m[2], l[2]); split3(v.w, h[3], m[3], l[3]);
    reinterpret_cast<uint2*>(g_rh)[i] = pack4(h);
    reinterpret_cast<uint2*>(g_rm)[i] = pack4(m);
    reinterpret_cast<uint2*>(g_rl)[i] = pack4(l);
}

__global__ void split_emb_kernel(const float* __restrict__ emb) {
    int i = blockIdx.x * blockDim.x + threadIdx.x;       // 0..1048575
    float4 v = reinterpret_cast<const float4*>(emb)[i];
    unsigned short h[4], m[4], l[4];
    split3(v.x, h[0], m[0], l[0]); split3(v.y, h[1], m[1], l[1]);
    split3(v.z, h[2], m[2], l[2]); split3(v.w, h[3], m[3], l[3]);
    reinterpret_cast<uint2*>(g_eh)[i] = pack4(h);
    reinterpret_cast<uint2*>(g_em)[i] = pack4(m);
    reinterpret_cast<uint2*>(g_el)[i] = pack4(l);
}

__global__ void enorm_kernel(const float* __restrict__ emb) {
    int gwarp = (blockIdx.x * blockDim.x + threadIdx.x) >> 5;  // 0..8191
    int lane  = threadIdx.x & 31;
    const float* e = emb + (size_t)gwarp * DIMV;
    float s = 0.f;
    #pragma unroll
    for (int d = lane; d < DIMV; d += 32) { float v = e[d]; s += v * v; }
    #pragma unroll
    for (int off = 16; off > 0; off >>= 1)
        s += __shfl_down_sync(0xffffffffu, s, off);
    if (lane == 0) g_enorm[gwarp] = s;
}

// ------------------------- cp.async stage loader ----------------------------
// Stage s: chunk = s>>3, ktile = s&7. 6 tiles x 16KB. Layout per tile:
// 128 rows x 128 bytes, 16B-column XOR swizzle: col ^ ((row&7)<<4).
__device__ __forceinline__ void issue_stage(int s, int rowBase, int q,
                                            unsigned dynb, int tid) {
    const int chunkI = s >> 3, ktI = s & 7;
    const unsigned buf = dynb + (unsigned)(s & 1) * 98304u;
    const int ebase = q * NK + chunkI * 128;
    #pragma unroll
    for (int j = 0; j < 24; ++j) {
        const int tile = j >> 2;
        const int within = tid + ((j & 3) << 8);   // 0..1023
        const int row = within >> 3, seg = within & 7;
        const uint4* src;
        int gi;
        if (tile == 0)      { src = g_rh; gi = (rowBase + row) * 64 + ktI * 8 + seg; }
        else if (tile == 1) { src = g_rm; gi = (rowBase + row) * 64 + ktI * 8 + seg; }
        else if (tile == 2) { src = g_rl; gi = (rowBase + row) * 64 + ktI * 8 + seg; }
        else {
            src = (tile == 3) ? g_eh : (tile == 4) ? g_em : g_el;
            gi = (ebase + row) * 64 + ktI * 8 + seg;
        }
        unsigned dst = buf + tile * 16384 + row * 128
                     + ((seg * 16) ^ ((row & 7) << 4));
        asm volatile("cp.async.cg.shared.global [%0], [%1], 16;"
                     :: "r"(dst), "l"(src + gi));
    }
}

// ------------------------- HMMA distance + argmin ---------------------------
// 128 CTAs x 256 threads; CTA: 128 rows x 1024 codes (8 chunks of 128).
// Effective K per chunk = 6 limb-pairs x 512. Warp grid 4(M) x 2(N),
// warp tile 32x64, mma m16n8k16 bf16->fp32.
__global__ void __launch_bounds__(256, 1) dist_hmma_kernel(int q) {
    extern __shared__ __align__(16) char dsm_raw[];
    __shared__ float sEn[128];
    __shared__ float sVal[128][2];
    __shared__ int   sIdx[128][2];

    const int tid  = threadIdx.x;
    const int lane = tid & 31;
    const int wid  = tid >> 5;
    const int mw = wid & 3, nw = wid >> 2;
    const int rowBase = blockIdx.x << 7;

    unsigned rawb = smem_u32(dsm_raw);
    unsigned dynb = (rawb + 1023u) & ~1023u;

    const int g = lane >> 2, tig = lane & 3;
    const int rlo = lane & 15, kh = lane >> 4;
    const int mwBase = mw * 32, nwBase = nw * 64;

    float best[2][2];
    int   bidx[2][2];
    #pragma unroll
    for (int a = 0; a < 2; ++a)
        #pragma unroll
        for (int b = 0; b < 2; ++b) { best[a][b] = 3.4e38f; bidx[a][b] = 0; }

    for (int chunk = 0; chunk < 8; ++chunk) {
        __syncthreads();                            // prev epilogue done
        if (tid < 128) sEn[tid] = g_enorm[q * NK + chunk * 128 + tid];

        float c[2][8][4];
        #pragma unroll
        for (int mi = 0; mi < 2; ++mi)
            #pragma unroll
            for (int nj = 0; nj < 8; ++nj)
                #pragma unroll
                for (int k = 0; k < 4; ++k) c[mi][nj][k] = 0.f;

        for (int kt = 0; kt < 8; ++kt) {
            const int s = chunk * 8 + kt;
            __syncthreads();                        // compute s-1 done (buffer reuse)
            if (s == 0) {
                issue_stage(0, rowBase, q, dynb, tid);
                asm volatile("cp.async.commit_group;" ::: "memory");
            }
            if (s + 1 < 64) {
                issue_stage(s + 1, rowBase, q, dynb, tid);
                asm volatile("cp.async.commit_group;" ::: "memory");
                asm volatile("cp.async.wait_group 1;" ::: "memory");
            } else {
                asm volatile("cp.async.wait_group 0;" ::: "memory");
            }
            __syncthreads();                        // stage s visible to all

            const unsigned stg = dynb + (unsigned)(s & 1) * 98304u;
            #pragma unroll
            for (int k0b = 0; k0b < 128; k0b += 32) {   // byte offset of k16 group
                const int colb = k0b + kh * 16;
                #pragma unroll
                for (int bl = 0; bl < 3; ++bl) {
                    unsigned Bf[4][4];
                    #pragma unroll
                    for (int njp = 0; njp < 4; ++njp) {
                        int row = nwBase + njp * 16 + rlo;
                        ldsm4(Bf[njp], stg + (3 + bl) * 16384 + row * 128
                                      + (colb ^ ((row & 7) << 4)));
                    }
                    // pairs: bl=0 -> A {h,m,l}; bl=1 -> {h,m}; bl=2 -> {h}
                    #pragma unroll
                    for (int al = 0; al < 3; ++al) {
                        if (al >= 3 - bl) break;
                        unsigned Af[2][4];
                        #pragma unroll
                        for (int mi = 0; mi < 2; ++mi) {
                            int row = mwBase + mi * 16 + rlo;
                            ldsm4(Af[mi], stg + al * 16384 + row * 128
                                         + (colb ^ ((row & 7) << 4)));
                        }
                        #pragma unroll
                        for (int mi = 0; mi < 2; ++mi)
                            #pragma unroll
                            for (int nj = 0; nj < 8; ++nj)
                                mma16816(c[mi][nj], Af[mi],
                                         Bf[nj >> 1][nj & 1],
                                         Bf[nj >> 1][2 + (nj & 1)]);
                    }
                }
            }
        }

        // per-chunk argmin epilogue (ascending col order => first-min tiebreak)
        #pragma unroll
        for (int mi = 0; mi < 2; ++mi)
            #pragma unroll
            for (int rh = 0; rh < 2; ++rh)
                #pragma unroll
                for (int nj = 0; nj < 8; ++nj)
                    #pragma unroll
                    for (int pc = 0; pc < 2; ++pc) {
                        const float acc = c[mi][nj][rh * 2 + pc];
                        const int colL = nwBase + nj * 8 + 2 * tig + pc;
                        const float d = fmaf(-2.f, acc, sEn[colL]);
                        if (d < best[mi][rh]) {
                            best[mi][rh] = d;
                            bidx[mi][rh] = chunk * 128 + colL;
                        }
                    }
    }

    // reduce across the 4 tig lanes (same rows, disjoint col sets)
    #pragma unroll
    for (int mi = 0; mi < 2; ++mi)
        #pragma unroll
        for (int rh = 0; rh < 2; ++rh) {
            float v = best[mi][rh];
            int   i = bidx[mi][rh];
            #pragma unroll
            for (int off = 1; off <= 2; off <<= 1) {
                float vo = __shfl_xor_sync(0xffffffffu, v, off);
                int   io = __shfl_xor_sync(0xffffffffu, i, off);
                if (vo < v || (vo == v && io < i)) { v = vo; i = io; }
            }
            if (tig == 0) {
                const int row = mwBase + mi * 16 + rh * 8 + g;
                sVal[row][nw] = v;
                sIdx[row][nw] = i;
            }
        }
    __syncthreads();
    if (tid < 128) {
        float v0 = sVal[tid][0]; int i0 = sIdx[tid][0];
        const float v1 = sVal[tid][1]; const int i1 = sIdx[tid][1];
        if (v1 < v0 || (v1 == v0 && i1 < i0)) { v0 = v1; i0 = i1; }
        g_idx[rowBase + tid] = i0;
    }
}

// ------------------------- residual update (+ split refresh) ----------------
__global__ void __launch_bounds__(256) update_kernel(
    const float* __restrict__ E, float* __restrict__ outF, int q)
{
    const int tid  = threadIdx.x;
    const int sub  = tid >> 7;
    const int lane = tid & 127;
    const int rowBase = blockIdx.x * 32;

    double s = 0.0;
    for (int it = 0; it < 16; ++it) {
        const int row = rowBase + it * 2 + sub;
        const int id  = g_idx[row];
        float4* r4 = reinterpret_cast<float4*>(g_res + (size_t)row * DIMV);
        const float4* e4 = reinterpret_cast<const float4*>(E + (size_t)id * DIMV);
        float4 r = r4[lane];
        const float4 e = e4[lane];
        r.x -= e.x; r.y -= e.y; r.z -= e.z; r.w -= e.w;
        r4[lane] = r;
        s += (double)(r.x * r.x + r.y * r.y + r.z * r.z + r.w * r.w);

        unsigned short h[4], m[4], l[4];
        split3(r.x, h[0], m[0], l[0]); split3(r.y, h[1], m[1], l[1]);
        split3(r.z, h[2], m[2], l[2]); split3(r.w, h[3], m[3], l[3]);
        const int u2 = row * 128 + lane;
        reinterpret_cast<uint2*>(g_rh)[u2] = pack4(h);
        reinterpret_cast<uint2*>(g_rm)[u2] = pack4(m);
        reinterpret_cast<uint2*>(g_rl)[u2] = pack4(l);

        if (lane == 0)
            outF[NDTOT + row * NQ + q] = (float)id;
    }

    #pragma unroll
    for (int off = 16; off > 0; off >>= 1)
        s += __shfl_down_sync(0xffffffffu, s, off);
    __shared__ double ws[8];
    const int wd = tid >> 5, ln = tid & 31;
    if (ln == 0) ws[wd] = s;
    __syncthreads();
    if (tid == 0) {
        double tot = 0.0;
        #pragma unroll
        for (int w = 0; w < 8; ++w) tot += ws[w];
        g_loss_part[q * 512 + blockIdx.x] = tot;
    }
}

// ------------------------- finalize -----------------------------------------
__global__ void finalize_kernel(const float* __restrict__ x,
                                float* __restrict__ outF)
{
    const int i = blockIdx.x * blockDim.x + threadIdx.x;
    const float4 xv = reinterpret_cast<const float4*>(x)[i];
    const float4 rv = reinterpret_cast<const float4*>(g_res)[i];
    float4 o;
    o.x = xv.x - rv.x; o.y = xv.y - rv.y;
    o.z = xv.z - rv.z; o.w = xv.w - rv.w;
    reinterpret_cast<float4*>(outF)[i] = o;

    if (blockIdx.x == 0 && threadIdx.x == 0) {
        double tot = 0.0;
        for (int k = 0; k < NQ * 512; ++k) tot += g_loss_part[k];
        outF[NDTOT + NROWS * NQ] = (float)(2.0 * tot / (double)NDTOT);
    }
}

// ---------------------------------------------------------------------------
extern "C" void kernel_launch(void* const* d_in, const int* in_sizes, int n_in,
                              void* d_out, int out_size)
{
    const float* x   = (const float*)d_in[0];
    const float* emb = (const float*)d_in[1];
    float* outF = (float*)d_out;

    cudaFuncSetAttribute(dist_hmma_kernel,
                         cudaFuncAttributeMaxDynamicSharedMemorySize, 197632);

    copy_split_kernel<<<8192, 256>>>(x);
    split_emb_kernel<<<4096, 256>>>(emb);
    enorm_kernel<<<1024, 256>>>(emb);

    for (int q = 0; q < NQ; ++q) {
        const float* Eq = emb + (size_t)q * NK * DIMV;
        dist_hmma_kernel<<<128, 256, 197632>>>(q);
        update_kernel<<<512, 256>>>(Eq, outF, q);
    }

    finalize_kernel<<<8192, 256>>>(x, outF);
}